// round 8
// baseline (speedup 1.0000x reference)
#include <cuda_runtime.h>
#include <stdint.h>

#define TT   64
#define NROW 1024
#define HH   32
#define ZSN  32
#define ZF   1024
#define ACT  6
#define EIN  10
#define XD   42          /* H + E */
#define G3H  96
#define GIN  1030
#define RPB  7           /* rows per scan block */
#define NTH  512
#define SCAN_GRID ((NROW + RPB - 1) / RPB)   /* 147 */
#define WPT  256                             /* worker blocks per t: 128 rowgrp x 2 colhalf */
#define WRK_GRID (TT * WPT)                  /* 16384 */

/* -------- scratch (static __device__, no allocations) -------- */
__device__ float         d_hbuf[TT * NROW * HH];        /* 8 MB   */
__device__ unsigned char d_zidx[TT * NROW * ZSN];       /* 2 MB   */
__device__ float         d_gum[(size_t)TT * NROW * ZF]; /* 256 MB */
__device__ int           d_flag[TT];
__device__ uint32_t      d_keys[2 * (TT + 1)];
__device__ float2        d_encWT2[(XD / 2) * ZF];
__device__ float2        d_dynWT2[(HH / 2) * ZF];
__device__ float         d_WihT[GIN * G3H];
__device__ float         d_WhhT[HH * G3H];

/* -------- threefry2x32, 20 rounds (JAX-exact, validated) -------- */
__device__ __forceinline__ void tf2x32_full(uint32_t k0, uint32_t k1,
                                            uint32_t c0, uint32_t c1,
                                            uint32_t &o0, uint32_t &o1) {
    uint32_t ks2 = k0 ^ k1 ^ 0x1BD11BDAu;
    uint32_t x0 = c0 + k0, x1 = c1 + k1;
#define TFR(r) { x0 += x1; x1 = __funnelshift_l(x1, x1, (r)); x1 ^= x0; }
    TFR(13) TFR(15) TFR(26) TFR(6);  x0 += k1;  x1 += ks2 + 1u;
    TFR(17) TFR(29) TFR(16) TFR(24); x0 += ks2; x1 += k0  + 2u;
    TFR(13) TFR(15) TFR(26) TFR(6);  x0 += k0;  x1 += k1  + 3u;
    TFR(17) TFR(29) TFR(16) TFR(24); x0 += k1;  x1 += ks2 + 4u;
    TFR(13) TFR(15) TFR(26) TFR(6);  x0 += ks2; x1 += k0  + 5u;
#undef TFR
    o0 = x0; o1 = x1;
}

/* uniform(minval=tiny,maxval=1) -> gumbel (bit-identical) */
__device__ __forceinline__ float gumbel32(uint32_t bits) {
    float f = __uint_as_float((bits >> 9) | 0x3f800000u) - 1.0f;
    const float TINY = 1.17549435082228750797e-38f;  /* FLT_MIN */
    float u = fmaxf(f, TINY);
    return -logf(-logf(u));
}

/* first-max-index argmax over 32 lanes (ties -> lowest lane) */
__device__ __forceinline__ int warp_argmax_fast(float v) {
    uint32_t s = __float_as_uint(v);
    uint32_t ord = (s & 0x80000000u) ? ~s : (s | 0x80000000u);
    uint32_t m = __reduce_max_sync(0xffffffffu, ord);
    return __ffs(__ballot_sync(0xffffffffu, ord == m)) - 1;
}

/* -------- prep: weight repack + keys + flag reset -------- */
#define PREP_TOTAL (XD * ZF + HH * ZF + G3H * GIN + G3H * HH + (TT + 1) + TT)
__global__ void prep_kernel(const float *__restrict__ encW,
                            const float *__restrict__ dynW,
                            const float *__restrict__ Wih,
                            const float *__restrict__ Whh) {
    int i = blockIdx.x * blockDim.x + threadIdx.x;
    if (i < XD * ZF) {
        int o = i / XD, k = i % XD;
        ((float *)d_encWT2)[(k >> 1) * 2 * ZF + 2 * o + (k & 1)] = encW[i];
        return;
    }
    i -= XD * ZF;
    if (i < HH * ZF) {
        int o = i / HH, k = i % HH;
        ((float *)d_dynWT2)[(k >> 1) * 2 * ZF + 2 * o + (k & 1)] = dynW[i];
        return;
    }
    i -= HH * ZF;
    if (i < G3H * GIN) { int o = i / GIN, c = i % GIN; d_WihT[c * G3H + o] = Wih[i]; return; }
    i -= G3H * GIN;
    if (i < G3H * HH) { int o = i / HH, k = i % HH; d_WhhT[k * G3H + o] = Whh[i]; return; }
    i -= G3H * HH;
    if (i < TT + 1) {
        uint32_t o0, o1;
        tf2x32_full(0u, 42u, 0u, (uint32_t)i, o0, o1);
        d_keys[2 * i] = o0; d_keys[2 * i + 1] = o1;
        return;
    }
    i -= TT + 1;
    if (i < TT) d_flag[i] = 0;
}

/* -------- gumbel precompute for the scan (unchanged, validated) -------- */
__global__ __launch_bounds__(256) void gz_kernel() {
    const int t = blockIdx.y, n = blockIdx.x;
    const uint32_t k0 = d_keys[2 * t], k1 = d_keys[2 * t + 1];
    const int j0 = threadIdx.x * 4;
    uint32_t e = (uint32_t)(n * ZF + j0);
    uint32_t b0, b1;
    float4 r;
    tf2x32_full(k0, k1, 0u, e + 0u, b0, b1); r.x = gumbel32(b0 ^ b1);
    tf2x32_full(k0, k1, 0u, e + 1u, b0, b1); r.y = gumbel32(b0 ^ b1);
    tf2x32_full(k0, k1, 0u, e + 2u, b0, b1); r.z = gumbel32(b0 ^ b1);
    tf2x32_full(k0, k1, 0u, e + 3u, b0, b1); r.w = gumbel32(b0 ^ b1);
    *reinterpret_cast<float4 *>(&d_gum[((size_t)t * NROW + n) * ZF + j0]) = r;
}

/* encoder logits + sample for one column, gumbels preloaded (round-5 math) */
__device__ __forceinline__ void enc_col_lean(
    int jc, int r0, int NR, int lane, int t, float encb, const float *g,
    const float (*sh_x)[XD], unsigned char (*sh_idx)[ZSN],
    float *__restrict__ z_out) {
    float acc[RPB];
#pragma unroll
    for (int i = 0; i < RPB; ++i) acc[i] = 0.f;
#pragma unroll
    for (int kk = 0; kk < XD / 2; ++kk) {
        float2 w = d_encWT2[kk * ZF + jc];
#pragma unroll
        for (int i = 0; i < RPB; ++i) {
            if (i < NR) {
                acc[i] = fmaf(w.x, sh_x[i][2 * kk], acc[i]);
                acc[i] = fmaf(w.y, sh_x[i][2 * kk + 1], acc[i]);
            }
        }
    }
#pragma unroll
    for (int i = 0; i < RPB; ++i) {
        if (i < NR) {
            int n = r0 + i;
            float v = (acc[i] + encb) + g[i];
            int bi = warp_argmax_fast(v);
            z_out[((size_t)t * NROW + n) * ZF + jc] = (lane == bi) ? 1.0f : 0.0f;
            if (lane == 0) {
                int zs = jc >> 5;
                sh_idx[i][zs] = (unsigned char)bi;
                d_zidx[((size_t)t * NROW + n) * ZSN + zs] = (unsigned char)bi;
            }
        }
    }
}

/* -------- mega-kernel: scan blocks (0..146) + dyn worker blocks -------- */
__global__ __launch_bounds__(NTH, 2) void rssm_mega(
    const float *__restrict__ x, const float *__restrict__ a,
    const float *__restrict__ h0, const float *__restrict__ enc_b,
    const float *__restrict__ bih, const float *__restrict__ bhh,
    const float *__restrict__ dynb,
    float *__restrict__ z_out, float *__restrict__ zp_out) {
    const int tid = threadIdx.x;
    const int lane = tid & 31;

    if (blockIdx.x < SCAN_GRID) {
        /* ================= SCAN ROLE ================= */
        const int jA = tid, jB = tid + NTH;
        const int r0 = blockIdx.x * RPB;
        const int NR = (NROW - r0 < RPB) ? (NROW - r0) : RPB;

        __shared__ float sh_h[RPB][HH];
        __shared__ float sh_x[RPB][XD];
        __shared__ float sh_a[RPB][ACT];
        __shared__ float sh_g[RPB][2][G3H];
        __shared__ unsigned char sh_idx[RPB][ZSN];

        const float encbA = enc_b[jA], encbB = enc_b[jB];

        for (int t = 0; t < TT; ++t) {
            /* prefetch gumbels for both columns */
            float gA[RPB], gB[RPB];
#pragma unroll
            for (int i = 0; i < RPB; ++i) {
                if (i < NR) {
                    gA[i] = __ldcs(&d_gum[((size_t)t * NROW + (r0 + i)) * ZF + jA]);
                    gB[i] = __ldcs(&d_gum[((size_t)t * NROW + (r0 + i)) * ZF + jB]);
                }
            }

            if (t == 0) {
                if (tid < NR * HH) {
                    int r = tid >> 5, ii = tid & 31;
                    int n = r0 + r;
                    float hv = h0[n * HH + ii];
                    sh_h[r][ii] = hv;
                    d_hbuf[(0 * NROW + n) * HH + ii] = hv;
                }
                __syncthreads();
            } else {
                if (tid < NR * ACT) {
                    int r = tid / ACT, c = tid % ACT;
                    sh_a[r][c] = a[((size_t)(t - 1) * NROW + (r0 + r)) * ACT + c];
                }
                __syncthreads();
                for (int task = tid; task < NR * 2 * G3H; task += NTH) {
                    int r = task / (2 * G3H);
                    int rem = task - r * (2 * G3H);
                    int kind = rem / G3H;
                    int o = rem - kind * G3H;
                    float acc = 0.f;
                    if (kind == 0) {
#pragma unroll
                        for (int zs = 0; zs < ZSN; ++zs)
                            acc += d_WihT[((zs << 5) + sh_idx[r][zs]) * G3H + o];
#pragma unroll
                        for (int c = 0; c < ACT; ++c)
                            acc = fmaf(d_WihT[(ZF + c) * G3H + o], sh_a[r][c], acc);
                        acc += bih[o];
                    } else {
#pragma unroll
                        for (int k = 0; k < HH; ++k)
                            acc = fmaf(d_WhhT[k * G3H + o], sh_h[r][k], acc);
                        acc += bhh[o];
                    }
                    sh_g[r][kind][o] = acc;
                }
                __syncthreads();
                if (tid < NR * HH) {
                    int r = tid >> 5, ii = tid & 31;
                    float xr = sh_g[r][0][ii], xz = sh_g[r][0][HH + ii], xn = sh_g[r][0][2 * HH + ii];
                    float hr = sh_g[r][1][ii], hz = sh_g[r][1][HH + ii], hn = sh_g[r][1][2 * HH + ii];
                    float rr = 1.0f / (1.0f + expf(-(xr + hr)));
                    float uu = 1.0f / (1.0f + expf(-(xz + hz)));
                    float nn = tanhf(xn + rr * hn);
                    float hp = sh_h[r][ii];
                    float hv = (1.0f - uu) * nn + uu * hp;
                    sh_h[r][ii] = hv;
                    d_hbuf[((size_t)t * NROW + (r0 + r)) * HH + ii] = hv;
                }
                __syncthreads();
            }
            /* release h[t] for dyn workers */
            if (tid == 0) {
                __threadfence();
                atomicAdd(&d_flag[t], 1);
            }
            /* encoder input: concat(h, e_t) */
            if (tid < NR * XD) {
                int r = tid / XD, k = tid - r * XD;
                sh_x[r][k] = (k < HH) ? sh_h[r][k]
                                      : x[((size_t)t * NROW + (r0 + r)) * EIN + (k - HH)];
            }
            __syncthreads();

            enc_col_lean(jA, r0, NR, lane, t, encbA, gA, sh_x, sh_idx, z_out);
            enc_col_lean(jB, r0, NR, lane, t, encbB, gB, sh_x, sh_idx, z_out);

            __syncthreads();
        }
    } else {
        /* ================= DYN WORKER ROLE ================= */
        const int b = blockIdx.x - SCAN_GRID;
        const int t = b >> 8;               /* 256 workers per t */
        const int r = b & 255;
        const int m0 = (t << 10) + ((r >> 1) << 3);   /* 8 rows */
        const int j = ((r & 1) << 9) + tid;           /* col half */

        __shared__ float sh[8][HH];

        if (tid == 0) {
            while (atomicAdd(&d_flag[t], 0) < SCAN_GRID) __nanosleep(128);
            __threadfence();
        }
        __syncthreads();

        if (tid < 8 * HH)
            sh[tid >> 5][tid & 31] =
                __ldcg(&d_hbuf[(size_t)(m0 + (tid >> 5)) * HH + (tid & 31)]);
        __syncthreads();

        const float db = dynb[j];
        float acc[8];
#pragma unroll
        for (int i = 0; i < 8; ++i) acc[i] = 0.f;
#pragma unroll
        for (int kk = 0; kk < HH / 2; ++kk) {
            float2 w = d_dynWT2[kk * ZF + j];
#pragma unroll
            for (int i = 0; i < 8; ++i) {
                acc[i] = fmaf(w.x, sh[i][2 * kk], acc[i]);
                acc[i] = fmaf(w.y, sh[i][2 * kk + 1], acc[i]);
            }
        }
        const uint32_t kd0 = d_keys[2 * TT], kd1 = d_keys[2 * TT + 1];
#pragma unroll
        for (int i = 0; i < 8; ++i) {
            uint32_t e = (uint32_t)((m0 + i) * ZF + j);
            uint32_t b0, b1;
            tf2x32_full(kd0, kd1, 0u, e, b0, b1);
            float v = (acc[i] + db) + gumbel32(b0 ^ b1);
            int bi = warp_argmax_fast(v);
            zp_out[(size_t)(m0 + i) * ZF + j] = (lane == bi) ? 1.0f : 0.0f;
        }
    }
}

/* -------- decoder / reward / continue heads -------- */
__global__ void head_kernel(const float *__restrict__ decW,
                            const float *__restrict__ decb,
                            const float *__restrict__ rewW,
                            const float *__restrict__ conW,
                            const float *__restrict__ conb,
                            float *__restrict__ x_logits,
                            float *__restrict__ r_loc,
                            float *__restrict__ c_logits) {
    int m = blockIdx.x * blockDim.x + threadIdx.x;
    if (m >= TT * NROW) return;
    float h[HH];
#pragma unroll
    for (int k = 0; k < HH; ++k) h[k] = d_hbuf[(size_t)m * HH + k];
    float rv = 0.f, cv = 0.f;
#pragma unroll
    for (int k = 0; k < HH; ++k) {
        rv = fmaf(rewW[k], h[k], rv);
        cv = fmaf(conW[k], h[k], cv);
    }
    r_loc[m] = rv;
    c_logits[m] = cv + conb[0];
    unsigned char zi[ZSN];
#pragma unroll
    for (int zs = 0; zs < ZSN; ++zs) zi[zs] = d_zidx[(size_t)m * ZSN + zs];
#pragma unroll
    for (int o = 0; o < EIN; ++o) {
        const float *w = decW + (size_t)o * (HH + ZF);
        float acc = 0.f;
#pragma unroll
        for (int k = 0; k < HH; ++k) acc = fmaf(w[k], h[k], acc);
#pragma unroll
        for (int zs = 0; zs < ZSN; ++zs) acc += w[HH + (zs << 5) + zi[zs]];
        x_logits[(size_t)m * EIN + o] = acc + decb[o];
    }
}

/* -------- launch -------- */
extern "C" void kernel_launch(void *const *d_in, const int *in_sizes, int n_in,
                              void *d_out, int out_size) {
    const float *x    = (const float *)d_in[0];
    const float *a    = (const float *)d_in[1];
    const float *h0   = (const float *)d_in[2];
    const float *encW = (const float *)d_in[3];
    const float *encb = (const float *)d_in[4];
    const float *Wih  = (const float *)d_in[5];
    const float *Whh  = (const float *)d_in[6];
    const float *bih  = (const float *)d_in[7];
    const float *bhh  = (const float *)d_in[8];
    const float *decW = (const float *)d_in[9];
    const float *decb = (const float *)d_in[10];
    const float *dynW = (const float *)d_in[11];
    const float *dynb = (const float *)d_in[12];
    const float *rewW = (const float *)d_in[13];
    const float *conW = (const float *)d_in[14];
    const float *conb = (const float *)d_in[15];

    float *out      = (float *)d_out;
    float *x_logits = out;                 /* 64*1024*10   = 655360   */
    float *r_loc    = out + 655360;        /* 64*1024*1    = 65536    */
    float *c_logits = out + 720896;        /* 64*1024*1    = 65536    */
    float *z        = out + 786432;        /* 64*1024*1024 = 67108864 */
    float *zp       = out + 67895296;      /* 64*1024*1024 = 67108864 */

    prep_kernel<<<(PREP_TOTAL + 255) / 256, 256>>>(encW, dynW, Wih, Whh);
    gz_kernel<<<dim3(NROW, TT), 256>>>();
    rssm_mega<<<SCAN_GRID + WRK_GRID, NTH>>>(x, a, h0, encb, bih, bhh, dynb, z, zp);
    head_kernel<<<(TT * NROW + 127) / 128, 128>>>(decW, decb, rewW, conW, conb,
                                                  x_logits, r_loc, c_logits);
}

// round 9
// speedup vs baseline: 1.3340x; 1.3340x over previous
#include <cuda_runtime.h>
#include <stdint.h>

#define TT   64
#define NROW 1024
#define HH   32
#define ZSN  32
#define ZF   1024
#define ACT  6
#define EIN  10
#define XD   42          /* H + E */
#define G3H  96
#define GIN  1030
#define RPB  7           /* rows per scan block */
#define SCAN_GRID ((NROW + RPB - 1) / RPB)   /* 147 */

/* -------- scratch (static __device__, no allocations) -------- */
__device__ float         d_hbuf[TT * NROW * HH];        /* 8 MB   */
__device__ unsigned char d_zidx[TT * NROW * ZSN];       /* 2 MB   */
__device__ float         d_gum[(size_t)TT * NROW * ZF]; /* 256 MB */
__device__ uint32_t      d_keys[2 * (TT + 1)];
__device__ float2        d_encWT2[(XD / 2) * ZF];
__device__ float2        d_dynWT2[(HH / 2) * ZF];
__device__ float         d_WihT[GIN * G3H];
__device__ float         d_WhhT[HH * G3H];

/* -------- threefry2x32, 20 rounds (JAX-exact, validated) -------- */
__device__ __forceinline__ void tf2x32_full(uint32_t k0, uint32_t k1,
                                            uint32_t c0, uint32_t c1,
                                            uint32_t &o0, uint32_t &o1) {
    uint32_t ks2 = k0 ^ k1 ^ 0x1BD11BDAu;
    uint32_t x0 = c0 + k0, x1 = c1 + k1;
#define TFR(r) { x0 += x1; x1 = __funnelshift_l(x1, x1, (r)); x1 ^= x0; }
    TFR(13) TFR(15) TFR(26) TFR(6);  x0 += k1;  x1 += ks2 + 1u;
    TFR(17) TFR(29) TFR(16) TFR(24); x0 += ks2; x1 += k0  + 2u;
    TFR(13) TFR(15) TFR(26) TFR(6);  x0 += k0;  x1 += k1  + 3u;
    TFR(17) TFR(29) TFR(16) TFR(24); x0 += k1;  x1 += ks2 + 4u;
    TFR(13) TFR(15) TFR(26) TFR(6);  x0 += ks2; x1 += k0  + 5u;
#undef TFR
    o0 = x0; o1 = x1;
}

/* uniform(minval=tiny,maxval=1) -> gumbel (bit-identical) */
__device__ __forceinline__ float gumbel32(uint32_t bits) {
    float f = __uint_as_float((bits >> 9) | 0x3f800000u) - 1.0f;
    const float TINY = 1.17549435082228750797e-38f;  /* FLT_MIN */
    float u = fmaxf(f, TINY);
    return -logf(-logf(u));
}

/* first-max-index argmax over 32 lanes (ties -> lowest lane) */
__device__ __forceinline__ int warp_argmax_fast(float v) {
    uint32_t s = __float_as_uint(v);
    uint32_t ord = (s & 0x80000000u) ? ~s : (s | 0x80000000u);
    uint32_t m = __reduce_max_sync(0xffffffffu, ord);
    return __ffs(__ballot_sync(0xffffffffu, ord == m)) - 1;
}

/* -------- prep: weight repack + keys -------- */
#define PREP_TOTAL (XD * ZF + HH * ZF + G3H * GIN + G3H * HH + (TT + 1))
__global__ void prep_kernel(const float *__restrict__ encW,
                            const float *__restrict__ dynW,
                            const float *__restrict__ Wih,
                            const float *__restrict__ Whh) {
    int i = blockIdx.x * blockDim.x + threadIdx.x;
    if (i < XD * ZF) {
        int o = i / XD, k = i % XD;
        ((float *)d_encWT2)[(k >> 1) * 2 * ZF + 2 * o + (k & 1)] = encW[i];
        return;
    }
    i -= XD * ZF;
    if (i < HH * ZF) {
        int o = i / HH, k = i % HH;
        ((float *)d_dynWT2)[(k >> 1) * 2 * ZF + 2 * o + (k & 1)] = dynW[i];
        return;
    }
    i -= HH * ZF;
    if (i < G3H * GIN) { int o = i / GIN, c = i % GIN; d_WihT[c * G3H + o] = Wih[i]; return; }
    i -= G3H * GIN;
    if (i < G3H * HH) { int o = i / HH, k = i % HH; d_WhhT[k * G3H + o] = Whh[i]; return; }
    i -= G3H * HH;
    if (i < TT + 1) {
        uint32_t o0, o1;
        tf2x32_full(0u, 42u, 0u, (uint32_t)i, o0, o1);
        d_keys[2 * i] = o0; d_keys[2 * i + 1] = o1;
    }
}

/* -------- gumbel precompute: 8 independent chains per thread -------- */
__global__ __launch_bounds__(256) void gz_kernel() {
    const int t = blockIdx.x >> 9;                 /* 512 blocks per t */
    const uint32_t k0 = d_keys[2 * t], k1 = d_keys[2 * t + 1];
    const uint32_t base = (((blockIdx.x & 511) << 8) + threadIdx.x) << 3;
    uint32_t b0, b1;
    float4 r0, r1;
    tf2x32_full(k0, k1, 0u, base + 0u, b0, b1); r0.x = gumbel32(b0 ^ b1);
    tf2x32_full(k0, k1, 0u, base + 1u, b0, b1); r0.y = gumbel32(b0 ^ b1);
    tf2x32_full(k0, k1, 0u, base + 2u, b0, b1); r0.z = gumbel32(b0 ^ b1);
    tf2x32_full(k0, k1, 0u, base + 3u, b0, b1); r0.w = gumbel32(b0 ^ b1);
    tf2x32_full(k0, k1, 0u, base + 4u, b0, b1); r1.x = gumbel32(b0 ^ b1);
    tf2x32_full(k0, k1, 0u, base + 5u, b0, b1); r1.y = gumbel32(b0 ^ b1);
    tf2x32_full(k0, k1, 0u, base + 6u, b0, b1); r1.z = gumbel32(b0 ^ b1);
    tf2x32_full(k0, k1, 0u, base + 7u, b0, b1); r1.w = gumbel32(b0 ^ b1);
    float4 *dst = reinterpret_cast<float4 *>(&d_gum[(size_t)t * NROW * ZF + base]);
    dst[0] = r0;
    dst[1] = r1;
}

/* -------- fused sequential scan: 7 rows/block, 3 syncs/step -------- */
__global__ __launch_bounds__(1024, 1) void rssm_scan(
    const float *__restrict__ x, const float *__restrict__ a,
    const float *__restrict__ h0, const float *__restrict__ enc_b,
    const float *__restrict__ bih, const float *__restrict__ bhh,
    float *__restrict__ z_out) {
    const int tid = threadIdx.x;
    const int j = tid;
    const int lane = tid & 31;
    const int r0 = blockIdx.x * RPB;
    const int NR = (NROW - r0 < RPB) ? (NROW - r0) : RPB;

    __shared__ float sh_h[RPB][HH];
    __shared__ float sh_e[RPB][EIN];
    __shared__ float sh_a[RPB][ACT];
    __shared__ float sh_g[RPB][2][G3H];
    __shared__ unsigned char sh_idx[RPB][ZSN];

    const float encb = enc_b[j];
    const int NTASK = NR * 2 * G3H;      /* gate tasks */
    const int ETASK = NR * EIN;          /* sh_e load tasks */

    for (int t = 0; t < TT; ++t) {
        /* gumbel prefetch (independent of all in-step work) */
        float g[RPB];
#pragma unroll
        for (int i = 0; i < RPB; ++i)
            if (i < NR) g[i] = __ldcs(&d_gum[((size_t)t * NROW + (r0 + i)) * ZF + j]);

        if (t == 0) {
            /* prologue: h0 -> sh_h + hbuf; load sh_e[0] */
            if (tid < NR * HH) {
                int r = tid >> 5, ii = tid & 31;
                int n = r0 + r;
                float hv = h0[n * HH + ii];
                sh_h[r][ii] = hv;
                d_hbuf[(0 * NROW + n) * HH + ii] = hv;
            } else if (tid < NR * HH + ETASK) {
                int q = tid - NR * HH;
                int r = q / EIN, k = q - r * EIN;
                sh_e[r][k] = x[((size_t)0 * NROW + (r0 + r)) * EIN + k];
            }
            __syncthreads();
        } else {
            /* phase B: gates (read sh_idx, sh_a, sh_h of t-1) + sh_e[t] load */
            for (int task = tid; task < NTASK + ETASK; task += 1024) {
                if (task < NTASK) {
                    int r = task / (2 * G3H);
                    int rem = task - r * (2 * G3H);
                    int kind = rem / G3H;
                    int o = rem - kind * G3H;
                    float acc = 0.f;
                    if (kind == 0) {
#pragma unroll
                        for (int zs = 0; zs < ZSN; ++zs)
                            acc += d_WihT[((zs << 5) + sh_idx[r][zs]) * G3H + o];
#pragma unroll
                        for (int c = 0; c < ACT; ++c)
                            acc = fmaf(d_WihT[(ZF + c) * G3H + o], sh_a[r][c], acc);
                        acc += bih[o];
                    } else {
#pragma unroll
                        for (int k = 0; k < HH; ++k)
                            acc = fmaf(d_WhhT[k * G3H + o], sh_h[r][k], acc);
                        acc += bhh[o];
                    }
                    sh_g[r][kind][o] = acc;
                } else {
                    int q = task - NTASK;
                    int r = q / EIN, k = q - r * EIN;
                    sh_e[r][k] = x[((size_t)t * NROW + (r0 + r)) * EIN + k];
                }
            }
            __syncthreads();
            /* phase C: gate nonlinearity + h update */
            if (tid < NR * HH) {
                int r = tid >> 5, ii = tid & 31;
                float xr = sh_g[r][0][ii], xz = sh_g[r][0][HH + ii], xn = sh_g[r][0][2 * HH + ii];
                float hr = sh_g[r][1][ii], hz = sh_g[r][1][HH + ii], hn = sh_g[r][1][2 * HH + ii];
                float rr = 1.0f / (1.0f + expf(-(xr + hr)));
                float uu = 1.0f / (1.0f + expf(-(xz + hz)));
                float nn = tanhf(xn + rr * hn);
                float hp = sh_h[r][ii];
                float hv = (1.0f - uu) * nn + uu * hp;
                sh_h[r][ii] = hv;
                d_hbuf[((size_t)t * NROW + (r0 + r)) * HH + ii] = hv;
            }
            __syncthreads();
        }

        /* phase D: encoder logits (reads sh_h + sh_e; identical FMA order),
           sample, and preload a[t] for next step's gates. */
        float acc[RPB];
#pragma unroll
        for (int i = 0; i < RPB; ++i) acc[i] = 0.f;
#pragma unroll
        for (int kk = 0; kk < HH / 2; ++kk) {       /* kk 0..15: h part */
            float2 w = d_encWT2[kk * ZF + j];
#pragma unroll
            for (int i = 0; i < RPB; ++i) {
                if (i < NR) {
                    acc[i] = fmaf(w.x, sh_h[i][2 * kk], acc[i]);
                    acc[i] = fmaf(w.y, sh_h[i][2 * kk + 1], acc[i]);
                }
            }
        }
#pragma unroll
        for (int kk = HH / 2; kk < XD / 2; ++kk) {  /* kk 16..20: e part */
            float2 w = d_encWT2[kk * ZF + j];
#pragma unroll
            for (int i = 0; i < RPB; ++i) {
                if (i < NR) {
                    acc[i] = fmaf(w.x, sh_e[i][2 * kk - HH], acc[i]);
                    acc[i] = fmaf(w.y, sh_e[i][2 * kk + 1 - HH], acc[i]);
                }
            }
        }
        /* preload a[t] for the t+1 gates (sh_a not read in this phase) */
        if (tid < NR * ACT) {
            int r = tid / ACT, c = tid - r * ACT;
            sh_a[r][c] = a[((size_t)t * NROW + (r0 + r)) * ACT + c];
        }
#pragma unroll
        for (int i = 0; i < RPB; ++i) {
            if (i < NR) {
                float v = (acc[i] + encb) + g[i];
                int bi = warp_argmax_fast(v);
                int n = r0 + i;
                z_out[((size_t)t * NROW + n) * ZF + j] = (lane == bi) ? 1.0f : 0.0f;
                if (lane == 0) {
                    int zs = j >> 5;
                    sh_idx[i][zs] = (unsigned char)bi;
                    d_zidx[((size_t)t * NROW + n) * ZSN + zs] = (unsigned char)bi;
                }
            }
        }
        __syncthreads();
    }
}

/* -------- decoder / reward / continue heads -------- */
__global__ void head_kernel(const float *__restrict__ decW,
                            const float *__restrict__ decb,
                            const float *__restrict__ rewW,
                            const float *__restrict__ conW,
                            const float *__restrict__ conb,
                            float *__restrict__ x_logits,
                            float *__restrict__ r_loc,
                            float *__restrict__ c_logits) {
    int m = blockIdx.x * blockDim.x + threadIdx.x;
    if (m >= TT * NROW) return;
    float h[HH];
#pragma unroll
    for (int k = 0; k < HH; ++k) h[k] = d_hbuf[(size_t)m * HH + k];
    float rv = 0.f, cv = 0.f;
#pragma unroll
    for (int k = 0; k < HH; ++k) {
        rv = fmaf(rewW[k], h[k], rv);
        cv = fmaf(conW[k], h[k], cv);
    }
    r_loc[m] = rv;
    c_logits[m] = cv + conb[0];
    unsigned char zi[ZSN];
#pragma unroll
    for (int zs = 0; zs < ZSN; ++zs) zi[zs] = d_zidx[(size_t)m * ZSN + zs];
#pragma unroll
    for (int o = 0; o < EIN; ++o) {
        const float *w = decW + (size_t)o * (HH + ZF);
        float acc = 0.f;
#pragma unroll
        for (int k = 0; k < HH; ++k) acc = fmaf(w[k], h[k], acc);
#pragma unroll
        for (int zs = 0; zs < ZSN; ++zs) acc += w[HH + (zs << 5) + zi[zs]];
        x_logits[(size_t)m * EIN + o] = acc + decb[o];
    }
}

/* -------- dynamics logits + z_post sample (keys[T]) -------- */
#define DROWS 8
__global__ __launch_bounds__(256) void dyn_kernel(const float *__restrict__ dynb,
                                                  float *__restrict__ zp) {
    __shared__ float sh[DROWS][HH];
    const int tid = threadIdx.x;
    const int m0 = (blockIdx.x >> 2) * DROWS;
    const int j = (blockIdx.x & 3) * 256 + tid;
    const int lane = tid & 31;

    sh[tid >> 5][tid & 31] = d_hbuf[(size_t)(m0 + (tid >> 5)) * HH + (tid & 31)];
    __syncthreads();

    const float db = dynb[j];
    float acc[DROWS];
#pragma unroll
    for (int i = 0; i < DROWS; ++i) acc[i] = 0.f;
#pragma unroll
    for (int kk = 0; kk < HH / 2; ++kk) {
        float2 w = d_dynWT2[kk * ZF + j];
#pragma unroll
        for (int i = 0; i < DROWS; ++i) {
            acc[i] = fmaf(w.x, sh[i][2 * kk], acc[i]);
            acc[i] = fmaf(w.y, sh[i][2 * kk + 1], acc[i]);
        }
    }
    const uint32_t k0 = d_keys[2 * TT], k1 = d_keys[2 * TT + 1];
#pragma unroll
    for (int i = 0; i < DROWS; ++i) {
        uint32_t e = (uint32_t)((m0 + i) * ZF + j);
        uint32_t b0, b1;
        tf2x32_full(k0, k1, 0u, e, b0, b1);
        float v = (acc[i] + db) + gumbel32(b0 ^ b1);
        int bi = warp_argmax_fast(v);
        zp[(size_t)(m0 + i) * ZF + j] = (lane == bi) ? 1.0f : 0.0f;
    }
}

/* -------- launch -------- */
extern "C" void kernel_launch(void *const *d_in, const int *in_sizes, int n_in,
                              void *d_out, int out_size) {
    const float *x    = (const float *)d_in[0];
    const float *a    = (const float *)d_in[1];
    const float *h0   = (const float *)d_in[2];
    const float *encW = (const float *)d_in[3];
    const float *encb = (const float *)d_in[4];
    const float *Wih  = (const float *)d_in[5];
    const float *Whh  = (const float *)d_in[6];
    const float *bih  = (const float *)d_in[7];
    const float *bhh  = (const float *)d_in[8];
    const float *decW = (const float *)d_in[9];
    const float *decb = (const float *)d_in[10];
    const float *dynW = (const float *)d_in[11];
    const float *dynb = (const float *)d_in[12];
    const float *rewW = (const float *)d_in[13];
    const float *conW = (const float *)d_in[14];
    const float *conb = (const float *)d_in[15];

    float *out      = (float *)d_out;
    float *x_logits = out;                 /* 64*1024*10   = 655360   */
    float *r_loc    = out + 655360;        /* 64*1024*1    = 65536    */
    float *c_logits = out + 720896;        /* 64*1024*1    = 65536    */
    float *z        = out + 786432;        /* 64*1024*1024 = 67108864 */
    float *zp       = out + 67895296;      /* 64*1024*1024 = 67108864 */

    prep_kernel<<<(PREP_TOTAL + 255) / 256, 256>>>(encW, dynW, Wih, Whh);
    gz_kernel<<<TT * 512, 256>>>();
    rssm_scan<<<SCAN_GRID, 1024>>>(x, a, h0, encb, bih, bhh, z);
    head_kernel<<<(TT * NROW + 127) / 128, 128>>>(decW, decb, rewW, conW, conb,
                                                  x_logits, r_loc, c_logits);
    dyn_kernel<<<(TT * NROW / DROWS) * 4, 256>>>(dynb, zp);
}

// round 13
// speedup vs baseline: 1.3439x; 1.0074x over previous
#include <cuda_runtime.h>
#include <stdint.h>

#define TT   64
#define NROW 1024
#define HH   32
#define ZSN  32
#define ZF   1024
#define ACT  6
#define EIN  10
#define XD   42          /* H + E */
#define G3H  96
#define GIN  1030
#define RPB  7           /* rows per scan block */
#define SCAN_GRID ((NROW + RPB - 1) / RPB)   /* 147 */

/* -------- scratch (static __device__, no allocations) -------- */
__device__ float         d_hbuf[TT * NROW * HH];        /* 8 MB   */
__device__ unsigned char d_zidx[TT * NROW * ZSN];       /* 2 MB   */
__device__ float         d_gum[(size_t)TT * NROW * ZF]; /* 256 MB */
__device__ uint32_t      d_keys[2 * (TT + 1)];
__device__ float2        d_encWT2[(XD / 2) * ZF];
__device__ float2        d_dynWT2[(HH / 2) * ZF];
__device__ float         d_WihT[GIN * G3H];
__device__ float         d_WhhT[HH * G3H];

/* -------- threefry2x32, 20 rounds (JAX-exact, validated) -------- */
__device__ __forceinline__ void tf2x32_full(uint32_t k0, uint32_t k1,
                                            uint32_t c0, uint32_t c1,
                                            uint32_t &o0, uint32_t &o1) {
    uint32_t ks2 = k0 ^ k1 ^ 0x1BD11BDAu;
    uint32_t x0 = c0 + k0, x1 = c1 + k1;
#define TFR(r) { x0 += x1; x1 = __funnelshift_l(x1, x1, (r)); x1 ^= x0; }
    TFR(13) TFR(15) TFR(26) TFR(6);  x0 += k1;  x1 += ks2 + 1u;
    TFR(17) TFR(29) TFR(16) TFR(24); x0 += ks2; x1 += k0  + 2u;
    TFR(13) TFR(15) TFR(26) TFR(6);  x0 += k0;  x1 += k1  + 3u;
    TFR(17) TFR(29) TFR(16) TFR(24); x0 += k1;  x1 += ks2 + 4u;
    TFR(13) TFR(15) TFR(26) TFR(6);  x0 += ks2; x1 += k0  + 5u;
#undef TFR
    o0 = x0; o1 = x1;
}

/* uniform(minval=tiny,maxval=1) -> gumbel (bit-identical) */
__device__ __forceinline__ float gumbel32(uint32_t bits) {
    float f = __uint_as_float((bits >> 9) | 0x3f800000u) - 1.0f;
    const float TINY = 1.17549435082228750797e-38f;  /* FLT_MIN */
    float u = fmaxf(f, TINY);
    return -logf(-logf(u));
}

/* first-max-index argmax over 32 lanes (ties -> lowest lane) */
__device__ __forceinline__ int warp_argmax_fast(float v) {
    uint32_t s = __float_as_uint(v);
    uint32_t ord = (s & 0x80000000u) ? ~s : (s | 0x80000000u);
    uint32_t m = __reduce_max_sync(0xffffffffu, ord);
    return __ffs(__ballot_sync(0xffffffffu, ord == m)) - 1;
}

/* -------- prep: weight repack + keys -------- */
#define PREP_TOTAL (XD * ZF + HH * ZF + G3H * GIN + G3H * HH + (TT + 1))
__global__ void prep_kernel(const float *__restrict__ encW,
                            const float *__restrict__ dynW,
                            const float *__restrict__ Wih,
                            const float *__restrict__ Whh) {
    int i = blockIdx.x * blockDim.x + threadIdx.x;
    if (i < XD * ZF) {
        int o = i / XD, k = i % XD;
        ((float *)d_encWT2)[(k >> 1) * 2 * ZF + 2 * o + (k & 1)] = encW[i];
        return;
    }
    i -= XD * ZF;
    if (i < HH * ZF) {
        int o = i / HH, k = i % HH;
        ((float *)d_dynWT2)[(k >> 1) * 2 * ZF + 2 * o + (k & 1)] = dynW[i];
        return;
    }
    i -= HH * ZF;
    if (i < G3H * GIN) { int o = i / GIN, c = i % GIN; d_WihT[c * G3H + o] = Wih[i]; return; }
    i -= G3H * GIN;
    if (i < G3H * HH) { int o = i / HH, k = i % HH; d_WhhT[k * G3H + o] = Whh[i]; return; }
    i -= G3H * HH;
    if (i < TT + 1) {
        uint32_t o0, o1;
        tf2x32_full(0u, 42u, 0u, (uint32_t)i, o0, o1);
        d_keys[2 * i] = o0; d_keys[2 * i + 1] = o1;
    }
}

/* -------- gumbel precompute: 8 chains/thread, t DESCENDING so that the
   low-t slices are written last and stay resident in L2 for the scan. -------- */
__global__ __launch_bounds__(256) void gz_kernel() {
    const int t = (TT - 1) - (blockIdx.x >> 9);    /* 512 blocks per t */
    const uint32_t k0 = d_keys[2 * t], k1 = d_keys[2 * t + 1];
    const uint32_t base = (((blockIdx.x & 511) << 8) + threadIdx.x) << 3;
    uint32_t b0, b1;
    float4 r0, r1;
    tf2x32_full(k0, k1, 0u, base + 0u, b0, b1); r0.x = gumbel32(b0 ^ b1);
    tf2x32_full(k0, k1, 0u, base + 1u, b0, b1); r0.y = gumbel32(b0 ^ b1);
    tf2x32_full(k0, k1, 0u, base + 2u, b0, b1); r0.z = gumbel32(b0 ^ b1);
    tf2x32_full(k0, k1, 0u, base + 3u, b0, b1); r0.w = gumbel32(b0 ^ b1);
    tf2x32_full(k0, k1, 0u, base + 4u, b0, b1); r1.x = gumbel32(b0 ^ b1);
    tf2x32_full(k0, k1, 0u, base + 5u, b0, b1); r1.y = gumbel32(b0 ^ b1);
    tf2x32_full(k0, k1, 0u, base + 6u, b0, b1); r1.z = gumbel32(b0 ^ b1);
    tf2x32_full(k0, k1, 0u, base + 7u, b0, b1); r1.w = gumbel32(b0 ^ b1);
    float4 *dst = reinterpret_cast<float4 *>(&d_gum[(size_t)t * NROW * ZF + base]);
    dst[0] = r0;
    dst[1] = r1;
}

/* -------- fused sequential scan: 7 rows/block, deep prefetch -------- */
__global__ __launch_bounds__(1024, 1) void rssm_scan(
    const float *__restrict__ x, const float *__restrict__ a,
    const float *__restrict__ h0, const float *__restrict__ enc_b,
    const float *__restrict__ bih, const float *__restrict__ bhh,
    float *__restrict__ z_out) {
    const int tid = threadIdx.x;
    const int j = tid;
    const int lane = tid & 31;
    const int r0 = blockIdx.x * RPB;
    const int NR = (NROW - r0 < RPB) ? (NROW - r0) : RPB;

    __shared__ float sh_h[RPB][HH];
    __shared__ float sh_e[RPB][EIN];
    __shared__ float sh_a[RPB][ACT];
    __shared__ float sh_g[RPB][2][G3H];
    __shared__ unsigned char sh_idx[RPB][ZSN];

    const float encb = enc_b[j];
    const int NTASK = NR * 2 * G3H;      /* gate tasks (1344 for NR=7) */
    const int ETASK = NR * EIN;          /* x-load tasks (70) */
    /* e-loader threads: 512..512+ETASK-1 (idle in phase C otherwise) */
    const int eq = tid - 512;

    /* ---- pre-loop: g for t=0 ---- */
    float g_cur[RPB], g_next[RPB];
#pragma unroll
    for (int i = 0; i < RPB; ++i)
        if (i < NR) g_cur[i] = d_gum[((size_t)0 * NROW + (r0 + i)) * ZF + j];

    for (int t = 0; t < TT; ++t) {
        /* top-of-step prefetches (deep cover, consumed much later) */
        if (t + 1 < TT) {
#pragma unroll
            for (int i = 0; i < RPB; ++i)
                if (i < NR) g_next[i] = d_gum[((size_t)(t + 1) * NROW + (r0 + i)) * ZF + j];
        }
        float a_reg = 0.f;
        if (tid < NR * ACT) {
            int r = tid / ACT, c = tid - r * ACT;
            a_reg = a[((size_t)t * NROW + (r0 + r)) * ACT + c];   /* for step t+1 gates */
        }
        float e_reg = 0.f;
        if (eq >= 0 && eq < ETASK) {
            int r = eq / EIN, k = eq - r * EIN;
            e_reg = x[((size_t)t * NROW + (r0 + r)) * EIN + k];   /* for this step's phase D */
        }

        if (t == 0) {
            if (tid < NR * HH) {
                int r = tid >> 5, ii = tid & 31;
                int n = r0 + r;
                float hv = h0[n * HH + ii];
                sh_h[r][ii] = hv;
                d_hbuf[(0 * NROW + n) * HH + ii] = hv;
            }
            if (eq >= 0 && eq < ETASK) {
                int r = eq / EIN, k = eq - r * EIN;
                sh_e[r][k] = e_reg;
            }
            __syncthreads();
        } else {
            /* phase B: gate tasks (reads sh_idx, sh_a, sh_h of t-1) */
            for (int task = tid; task < NTASK; task += 1024) {
                int r = task / (2 * G3H);
                int rem = task - r * (2 * G3H);
                int kind = rem / G3H;
                int o = rem - kind * G3H;
                float acc = 0.f;
                if (kind == 0) {
#pragma unroll
                    for (int zs = 0; zs < ZSN; ++zs)
                        acc += d_WihT[((zs << 5) + sh_idx[r][zs]) * G3H + o];
#pragma unroll
                    for (int c = 0; c < ACT; ++c)
                        acc = fmaf(d_WihT[(ZF + c) * G3H + o], sh_a[r][c], acc);
                    acc += bih[o];
                } else {
#pragma unroll
                    for (int k = 0; k < HH; ++k)
                        acc = fmaf(d_WhhT[k * G3H + o], sh_h[r][k], acc);
                    acc += bhh[o];
                }
                sh_g[r][kind][o] = acc;
            }
            __syncthreads();
            /* phase C: gate nonlinearity + h update; e-loader threads store sh_e */
            if (tid < NR * HH) {
                int r = tid >> 5, ii = tid & 31;
                float xr = sh_g[r][0][ii], xz = sh_g[r][0][HH + ii], xn = sh_g[r][0][2 * HH + ii];
                float hr = sh_g[r][1][ii], hz = sh_g[r][1][HH + ii], hn = sh_g[r][1][2 * HH + ii];
                float rr = 1.0f / (1.0f + expf(-(xr + hr)));
                float uu = 1.0f / (1.0f + expf(-(xz + hz)));
                float nn = tanhf(xn + rr * hn);
                float hp = sh_h[r][ii];
                float hv = (1.0f - uu) * nn + uu * hp;
                sh_h[r][ii] = hv;
                d_hbuf[((size_t)t * NROW + (r0 + r)) * HH + ii] = hv;
            } else if (eq >= 0 && eq < ETASK) {
                int r = eq / EIN, k = eq - r * EIN;
                sh_e[r][k] = e_reg;
            }
            __syncthreads();
        }

        /* phase D: encoder logits (reads sh_h + sh_e; identical FMA order),
           sample, and stage a[t] for next step. */
        float acc[RPB];
#pragma unroll
        for (int i = 0; i < RPB; ++i) acc[i] = 0.f;
#pragma unroll
        for (int kk = 0; kk < HH / 2; ++kk) {       /* kk 0..15: h part */
            float2 w = d_encWT2[kk * ZF + j];
#pragma unroll
            for (int i = 0; i < RPB; ++i) {
                if (i < NR) {
                    acc[i] = fmaf(w.x, sh_h[i][2 * kk], acc[i]);
                    acc[i] = fmaf(w.y, sh_h[i][2 * kk + 1], acc[i]);
                }
            }
        }
#pragma unroll
        for (int kk = HH / 2; kk < XD / 2; ++kk) {  /* kk 16..20: e part */
            float2 w = d_encWT2[kk * ZF + j];
#pragma unroll
            for (int i = 0; i < RPB; ++i) {
                if (i < NR) {
                    acc[i] = fmaf(w.x, sh_e[i][2 * kk - HH], acc[i]);
                    acc[i] = fmaf(w.y, sh_e[i][2 * kk + 1 - HH], acc[i]);
                }
            }
        }
        /* stage a[t] into sh_a for step t+1's gates */
        if (tid < NR * ACT) {
            int r = tid / ACT, c = tid - r * ACT;
            sh_a[r][c] = a_reg;
        }
#pragma unroll
        for (int i = 0; i < RPB; ++i) {
            if (i < NR) {
                float v = (acc[i] + encb) + g_cur[i];
                int bi = warp_argmax_fast(v);
                int n = r0 + i;
                z_out[((size_t)t * NROW + n) * ZF + j] = (lane == bi) ? 1.0f : 0.0f;
                if (lane == 0) {
                    int zs = j >> 5;
                    sh_idx[i][zs] = (unsigned char)bi;
                    d_zidx[((size_t)t * NROW + n) * ZSN + zs] = (unsigned char)bi;
                }
            }
        }
#pragma unroll
        for (int i = 0; i < RPB; ++i) g_cur[i] = g_next[i];
        __syncthreads();
    }
}

/* -------- decoder / reward / continue heads -------- */
__global__ void head_kernel(const float *__restrict__ decW,
                            const float *__restrict__ decb,
                            const float *__restrict__ rewW,
                            const float *__restrict__ conW,
                            const float *__restrict__ conb,
                            float *__restrict__ x_logits,
                            float *__restrict__ r_loc,
                            float *__restrict__ c_logits) {
    int m = blockIdx.x * blockDim.x + threadIdx.x;
    if (m >= TT * NROW) return;
    float h[HH];
#pragma unroll
    for (int k = 0; k < HH; ++k) h[k] = d_hbuf[(size_t)m * HH + k];
    float rv = 0.f, cv = 0.f;
#pragma unroll
    for (int k = 0; k < HH; ++k) {
        rv = fmaf(rewW[k], h[k], rv);
        cv = fmaf(conW[k], h[k], cv);
    }
    r_loc[m] = rv;
    c_logits[m] = cv + conb[0];
    unsigned char zi[ZSN];
#pragma unroll
    for (int zs = 0; zs < ZSN; ++zs) zi[zs] = d_zidx[(size_t)m * ZSN + zs];
#pragma unroll
    for (int o = 0; o < EIN; ++o) {
        const float *w = decW + (size_t)o * (HH + ZF);
        float acc = 0.f;
#pragma unroll
        for (int k = 0; k < HH; ++k) acc = fmaf(w[k], h[k], acc);
#pragma unroll
        for (int zs = 0; zs < ZSN; ++zs) acc += w[HH + (zs << 5) + zi[zs]];
        x_logits[(size_t)m * EIN + o] = acc + decb[o];
    }
}

/* -------- dynamics logits + z_post sample (keys[T]) -------- */
#define DROWS 8
__global__ __launch_bounds__(256) void dyn_kernel(const float *__restrict__ dynb,
                                                  float *__restrict__ zp) {
    __shared__ float sh[DROWS][HH];
    const int tid = threadIdx.x;
    const int m0 = (blockIdx.x >> 2) * DROWS;
    const int j = (blockIdx.x & 3) * 256 + tid;
    const int lane = tid & 31;

    sh[tid >> 5][tid & 31] = d_hbuf[(size_t)(m0 + (tid >> 5)) * HH + (tid & 31)];
    __syncthreads();

    const float db = dynb[j];
    float acc[DROWS];
#pragma unroll
    for (int i = 0; i < DROWS; ++i) acc[i] = 0.f;
#pragma unroll
    for (int kk = 0; kk < HH / 2; ++kk) {
        float2 w = d_dynWT2[kk * ZF + j];
#pragma unroll
        for (int i = 0; i < DROWS; ++i) {
            acc[i] = fmaf(w.x, sh[i][2 * kk], acc[i]);
            acc[i] = fmaf(w.y, sh[i][2 * kk + 1], acc[i]);
        }
    }
    const uint32_t k0 = d_keys[2 * TT], k1 = d_keys[2 * TT + 1];
#pragma unroll
    for (int i = 0; i < DROWS; ++i) {
        uint32_t e = (uint32_t)((m0 + i) * ZF + j);
        uint32_t b0, b1;
        tf2x32_full(k0, k1, 0u, e, b0, b1);
        float v = (acc[i] + db) + gumbel32(b0 ^ b1);
        int bi = warp_argmax_fast(v);
        zp[(size_t)(m0 + i) * ZF + j] = (lane == bi) ? 1.0f : 0.0f;
    }
}

/* -------- launch -------- */
extern "C" void kernel_launch(void *const *d_in, const int *in_sizes, int n_in,
                              void *d_out, int out_size) {
    const float *x    = (const float *)d_in[0];
    const float *a    = (const float *)d_in[1];
    const float *h0   = (const float *)d_in[2];
    const float *encW = (const float *)d_in[3];
    const float *encb = (const float *)d_in[4];
    const float *Wih  = (const float *)d_in[5];
    const float *Whh  = (const float *)d_in[6];
    const float *bih  = (const float *)d_in[7];
    const float *bhh  = (const float *)d_in[8];
    const float *decW = (const float *)d_in[9];
    const float *decb = (const float *)d_in[10];
    const float *dynW = (const float *)d_in[11];
    const float *dynb = (const float *)d_in[12];
    const float *rewW = (const float *)d_in[13];
    const float *conW = (const float *)d_in[14];
    const float *conb = (const float *)d_in[15];

    float *out      = (float *)d_out;
    float *x_logits = out;                 /* 64*1024*10   = 655360   */
    float *r_loc    = out + 655360;        /* 64*1024*1    = 65536    */
    float *c_logits = out + 720896;        /* 64*1024*1    = 65536    */
    float *z        = out + 786432;        /* 64*1024*1024 = 67108864 */
    float *zp       = out + 67895296;      /* 64*1024*1024 = 67108864 */

    prep_kernel<<<(PREP_TOTAL + 255) / 256, 256>>>(encW, dynW, Wih, Whh);
    gz_kernel<<<TT * 512, 256>>>();
    rssm_scan<<<SCAN_GRID, 1024>>>(x, a, h0, encb, bih, bhh, z);
    head_kernel<<<(TT * NROW + 127) / 128, 128>>>(decW, decb, rewW, conW, conb,
                                                  x_logits, r_loc, c_logits);
    dyn_kernel<<<(TT * NROW / DROWS) * 4, 256>>>(dynb, zp);
}

// round 14
// speedup vs baseline: 1.3458x; 1.0014x over previous
#include <cuda_runtime.h>
#include <stdint.h>

#define TT   64
#define NROW 1024
#define HH   32
#define ZSN  32
#define ZF   1024
#define ACT  6
#define EIN  10
#define XD   42          /* H + E */
#define G3H  96
#define GIN  1030
#define RPB  7           /* rows per scan block */
#define SCAN_GRID ((NROW + RPB - 1) / RPB)   /* 147 */

/* -------- scratch (static __device__, no allocations) -------- */
__device__ float         d_hbuf[TT * NROW * HH];        /* 8 MB   */
__device__ unsigned char d_zidx[TT * NROW * ZSN];       /* 2 MB   */
__device__ float         d_gum[(size_t)TT * NROW * ZF]; /* 256 MB */
__device__ uint32_t      d_keys[2 * (TT + 1)];
__device__ float2        d_encWT2[(XD / 2) * ZF];
__device__ float2        d_dynWT2[(HH / 2) * ZF];
__device__ float         d_WihT[GIN * G3H];
__device__ float         d_WhhT[HH * G3H];

/* -------- threefry2x32, 20 rounds (JAX-exact, validated) --------
   Rotates are computed as IMAD.WIDE (fma pipe): p = x1 * 2^r puts
   (x1<<r) in lo(p) and (x1>>(32-r)) in hi(p); (lo|hi)^x0 is one LOP3.
   Pure integer identity -> bit-identical results, but shifts move off
   the saturated alu pipe onto the underused fma pipe.               */
#define TFR_IMAD(r)                                                      \
    {                                                                    \
        x0 += x1;                                                        \
        uint64_t p = (uint64_t)x1 * ((uint64_t)1u << (r));               \
        x1 = ((uint32_t)p | (uint32_t)(p >> 32)) ^ x0;                   \
    }

__device__ __forceinline__ void tf2x32_full(uint32_t k0, uint32_t k1,
                                            uint32_t c0, uint32_t c1,
                                            uint32_t &o0, uint32_t &o1) {
    uint32_t ks2 = k0 ^ k1 ^ 0x1BD11BDAu;
    uint32_t x0 = c0 + k0, x1 = c1 + k1;
    TFR_IMAD(13) TFR_IMAD(15) TFR_IMAD(26) TFR_IMAD(6)
    x0 += k1;  x1 += ks2 + 1u;
    TFR_IMAD(17) TFR_IMAD(29) TFR_IMAD(16) TFR_IMAD(24)
    x0 += ks2; x1 += k0  + 2u;
    TFR_IMAD(13) TFR_IMAD(15) TFR_IMAD(26) TFR_IMAD(6)
    x0 += k0;  x1 += k1  + 3u;
    TFR_IMAD(17) TFR_IMAD(29) TFR_IMAD(16) TFR_IMAD(24)
    x0 += k1;  x1 += ks2 + 4u;
    TFR_IMAD(13) TFR_IMAD(15) TFR_IMAD(26) TFR_IMAD(6)
    x0 += ks2; x1 += k0  + 5u;
    o0 = x0; o1 = x1;
}

/* uniform(minval=tiny,maxval=1) -> gumbel (bit-identical) */
__device__ __forceinline__ float gumbel32(uint32_t bits) {
    float f = __uint_as_float((bits >> 9) | 0x3f800000u) - 1.0f;
    const float TINY = 1.17549435082228750797e-38f;  /* FLT_MIN */
    float u = fmaxf(f, TINY);
    return -logf(-logf(u));
}

/* first-max-index argmax over 32 lanes (ties -> lowest lane) */
__device__ __forceinline__ int warp_argmax_fast(float v) {
    uint32_t s = __float_as_uint(v);
    uint32_t ord = (s & 0x80000000u) ? ~s : (s | 0x80000000u);
    uint32_t m = __reduce_max_sync(0xffffffffu, ord);
    return __ffs(__ballot_sync(0xffffffffu, ord == m)) - 1;
}

/* -------- prep: weight repack + keys -------- */
#define PREP_TOTAL (XD * ZF + HH * ZF + G3H * GIN + G3H * HH + (TT + 1))
__global__ void prep_kernel(const float *__restrict__ encW,
                            const float *__restrict__ dynW,
                            const float *__restrict__ Wih,
                            const float *__restrict__ Whh) {
    int i = blockIdx.x * blockDim.x + threadIdx.x;
    if (i < XD * ZF) {
        int o = i / XD, k = i % XD;
        ((float *)d_encWT2)[(k >> 1) * 2 * ZF + 2 * o + (k & 1)] = encW[i];
        return;
    }
    i -= XD * ZF;
    if (i < HH * ZF) {
        int o = i / HH, k = i % HH;
        ((float *)d_dynWT2)[(k >> 1) * 2 * ZF + 2 * o + (k & 1)] = dynW[i];
        return;
    }
    i -= HH * ZF;
    if (i < G3H * GIN) { int o = i / GIN, c = i % GIN; d_WihT[c * G3H + o] = Wih[i]; return; }
    i -= G3H * GIN;
    if (i < G3H * HH) { int o = i / HH, k = i % HH; d_WhhT[k * G3H + o] = Whh[i]; return; }
    i -= G3H * HH;
    if (i < TT + 1) {
        uint32_t o0, o1;
        tf2x32_full(0u, 42u, 0u, (uint32_t)i, o0, o1);
        d_keys[2 * i] = o0; d_keys[2 * i + 1] = o1;
    }
}

/* -------- gumbel precompute: 8 chains/thread, t DESCENDING so that the
   low-t slices are written last and stay resident in L2 for the scan. -------- */
__global__ __launch_bounds__(256) void gz_kernel() {
    const int t = (TT - 1) - (blockIdx.x >> 9);    /* 512 blocks per t */
    const uint32_t k0 = d_keys[2 * t], k1 = d_keys[2 * t + 1];
    const uint32_t base = (((blockIdx.x & 511) << 8) + threadIdx.x) << 3;
    uint32_t b0, b1;
    float4 r0, r1;
    tf2x32_full(k0, k1, 0u, base + 0u, b0, b1); r0.x = gumbel32(b0 ^ b1);
    tf2x32_full(k0, k1, 0u, base + 1u, b0, b1); r0.y = gumbel32(b0 ^ b1);
    tf2x32_full(k0, k1, 0u, base + 2u, b0, b1); r0.z = gumbel32(b0 ^ b1);
    tf2x32_full(k0, k1, 0u, base + 3u, b0, b1); r0.w = gumbel32(b0 ^ b1);
    tf2x32_full(k0, k1, 0u, base + 4u, b0, b1); r1.x = gumbel32(b0 ^ b1);
    tf2x32_full(k0, k1, 0u, base + 5u, b0, b1); r1.y = gumbel32(b0 ^ b1);
    tf2x32_full(k0, k1, 0u, base + 6u, b0, b1); r1.z = gumbel32(b0 ^ b1);
    tf2x32_full(k0, k1, 0u, base + 7u, b0, b1); r1.w = gumbel32(b0 ^ b1);
    float4 *dst = reinterpret_cast<float4 *>(&d_gum[(size_t)t * NROW * ZF + base]);
    dst[0] = r0;
    dst[1] = r1;
}

/* -------- fused sequential scan: 7 rows/block, deep prefetch -------- */
__global__ __launch_bounds__(1024, 1) void rssm_scan(
    const float *__restrict__ x, const float *__restrict__ a,
    const float *__restrict__ h0, const float *__restrict__ enc_b,
    const float *__restrict__ bih, const float *__restrict__ bhh,
    float *__restrict__ z_out) {
    const int tid = threadIdx.x;
    const int j = tid;
    const int lane = tid & 31;
    const int r0 = blockIdx.x * RPB;
    const int NR = (NROW - r0 < RPB) ? (NROW - r0) : RPB;

    __shared__ float sh_h[RPB][HH];
    __shared__ float sh_e[RPB][EIN];
    __shared__ float sh_a[RPB][ACT];
    __shared__ float sh_g[RPB][2][G3H];
    __shared__ unsigned char sh_idx[RPB][ZSN];

    const float encb = enc_b[j];
    const int NTASK = NR * 2 * G3H;      /* gate tasks (1344 for NR=7) */
    const int ETASK = NR * EIN;          /* x-load tasks (70) */
    const int eq = tid - 512;

    /* ---- pre-loop: g for t=0 ---- */
    float g_cur[RPB], g_next[RPB];
#pragma unroll
    for (int i = 0; i < RPB; ++i)
        if (i < NR) g_cur[i] = d_gum[((size_t)0 * NROW + (r0 + i)) * ZF + j];

    for (int t = 0; t < TT; ++t) {
        /* top-of-step prefetches (deep cover, consumed much later) */
        if (t + 1 < TT) {
#pragma unroll
            for (int i = 0; i < RPB; ++i)
                if (i < NR) g_next[i] = d_gum[((size_t)(t + 1) * NROW + (r0 + i)) * ZF + j];
        }
        float a_reg = 0.f;
        if (tid < NR * ACT) {
            int r = tid / ACT, c = tid - r * ACT;
            a_reg = a[((size_t)t * NROW + (r0 + r)) * ACT + c];   /* for step t+1 gates */
        }
        float e_reg = 0.f;
        if (eq >= 0 && eq < ETASK) {
            int r = eq / EIN, k = eq - r * EIN;
            e_reg = x[((size_t)t * NROW + (r0 + r)) * EIN + k];   /* for this step's phase D */
        }

        if (t == 0) {
            if (tid < NR * HH) {
                int r = tid >> 5, ii = tid & 31;
                int n = r0 + r;
                float hv = h0[n * HH + ii];
                sh_h[r][ii] = hv;
                d_hbuf[(0 * NROW + n) * HH + ii] = hv;
            }
            if (eq >= 0 && eq < ETASK) {
                int r = eq / EIN, k = eq - r * EIN;
                sh_e[r][k] = e_reg;
            }
            __syncthreads();
        } else {
            /* phase B: gate tasks (reads sh_idx, sh_a, sh_h of t-1) */
            for (int task = tid; task < NTASK; task += 1024) {
                int r = task / (2 * G3H);
                int rem = task - r * (2 * G3H);
                int kind = rem / G3H;
                int o = rem - kind * G3H;
                float acc = 0.f;
                if (kind == 0) {
#pragma unroll
                    for (int zs = 0; zs < ZSN; ++zs)
                        acc += d_WihT[((zs << 5) + sh_idx[r][zs]) * G3H + o];
#pragma unroll
                    for (int c = 0; c < ACT; ++c)
                        acc = fmaf(d_WihT[(ZF + c) * G3H + o], sh_a[r][c], acc);
                    acc += bih[o];
                } else {
#pragma unroll
                    for (int k = 0; k < HH; ++k)
                        acc = fmaf(d_WhhT[k * G3H + o], sh_h[r][k], acc);
                    acc += bhh[o];
                }
                sh_g[r][kind][o] = acc;
            }
            __syncthreads();
            /* phase C: gate nonlinearity + h update; e-loader threads store sh_e */
            if (tid < NR * HH) {
                int r = tid >> 5, ii = tid & 31;
                float xr = sh_g[r][0][ii], xz = sh_g[r][0][HH + ii], xn = sh_g[r][0][2 * HH + ii];
                float hr = sh_g[r][1][ii], hz = sh_g[r][1][HH + ii], hn = sh_g[r][1][2 * HH + ii];
                float rr = 1.0f / (1.0f + expf(-(xr + hr)));
                float uu = 1.0f / (1.0f + expf(-(xz + hz)));
                float nn = tanhf(xn + rr * hn);
                float hp = sh_h[r][ii];
                float hv = (1.0f - uu) * nn + uu * hp;
                sh_h[r][ii] = hv;
                d_hbuf[((size_t)t * NROW + (r0 + r)) * HH + ii] = hv;
            } else if (eq >= 0 && eq < ETASK) {
                int r = eq / EIN, k = eq - r * EIN;
                sh_e[r][k] = e_reg;
            }
            __syncthreads();
        }

        /* phase D: encoder logits (identical FMA order), sample, stage a[t] */
        float acc[RPB];
#pragma unroll
        for (int i = 0; i < RPB; ++i) acc[i] = 0.f;
#pragma unroll
        for (int kk = 0; kk < HH / 2; ++kk) {       /* kk 0..15: h part */
            float2 w = d_encWT2[kk * ZF + j];
#pragma unroll
            for (int i = 0; i < RPB; ++i) {
                if (i < NR) {
                    acc[i] = fmaf(w.x, sh_h[i][2 * kk], acc[i]);
                    acc[i] = fmaf(w.y, sh_h[i][2 * kk + 1], acc[i]);
                }
            }
        }
#pragma unroll
        for (int kk = HH / 2; kk < XD / 2; ++kk) {  /* kk 16..20: e part */
            float2 w = d_encWT2[kk * ZF + j];
#pragma unroll
            for (int i = 0; i < RPB; ++i) {
                if (i < NR) {
                    acc[i] = fmaf(w.x, sh_e[i][2 * kk - HH], acc[i]);
                    acc[i] = fmaf(w.y, sh_e[i][2 * kk + 1 - HH], acc[i]);
                }
            }
        }
        /* stage a[t] into sh_a for step t+1's gates */
        if (tid < NR * ACT) {
            int r = tid / ACT, c = tid - r * ACT;
            sh_a[r][c] = a_reg;
        }
#pragma unroll
        for (int i = 0; i < RPB; ++i) {
            if (i < NR) {
                float v = (acc[i] + encb) + g_cur[i];
                int bi = warp_argmax_fast(v);
                int n = r0 + i;
                z_out[((size_t)t * NROW + n) * ZF + j] = (lane == bi) ? 1.0f : 0.0f;
                if (lane == 0) {
                    int zs = j >> 5;
                    sh_idx[i][zs] = (unsigned char)bi;
                    d_zidx[((size_t)t * NROW + n) * ZSN + zs] = (unsigned char)bi;
                }
            }
        }
#pragma unroll
        for (int i = 0; i < RPB; ++i) g_cur[i] = g_next[i];
        __syncthreads();
    }
}

/* -------- decoder / reward / continue heads -------- */
__global__ void head_kernel(const float *__restrict__ decW,
                            const float *__restrict__ decb,
                            const float *__restrict__ rewW,
                            const float *__restrict__ conW,
                            const float *__restrict__ conb,
                            float *__restrict__ x_logits,
                            float *__restrict__ r_loc,
                            float *__restrict__ c_logits) {
    int m = blockIdx.x * blockDim.x + threadIdx.x;
    if (m >= TT * NROW) return;
    float h[HH];
#pragma unroll
    for (int k = 0; k < HH; ++k) h[k] = d_hbuf[(size_t)m * HH + k];
    float rv = 0.f, cv = 0.f;
#pragma unroll
    for (int k = 0; k < HH; ++k) {
        rv = fmaf(rewW[k], h[k], rv);
        cv = fmaf(conW[k], h[k], cv);
    }
    r_loc[m] = rv;
    c_logits[m] = cv + conb[0];
    unsigned char zi[ZSN];
#pragma unroll
    for (int zs = 0; zs < ZSN; ++zs) zi[zs] = d_zidx[(size_t)m * ZSN + zs];
#pragma unroll
    for (int o = 0; o < EIN; ++o) {
        const float *w = decW + (size_t)o * (HH + ZF);
        float acc = 0.f;
#pragma unroll
        for (int k = 0; k < HH; ++k) acc = fmaf(w[k], h[k], acc);
#pragma unroll
        for (int zs = 0; zs < ZSN; ++zs) acc += w[HH + (zs << 5) + zi[zs]];
        x_logits[(size_t)m * EIN + o] = acc + decb[o];
    }
}

/* -------- dynamics logits + z_post sample (keys[T]) -------- */
#define DROWS 8
__global__ __launch_bounds__(256) void dyn_kernel(const float *__restrict__ dynb,
                                                  float *__restrict__ zp) {
    __shared__ float sh[DROWS][HH];
    const int tid = threadIdx.x;
    const int m0 = (blockIdx.x >> 2) * DROWS;
    const int j = (blockIdx.x & 3) * 256 + tid;
    const int lane = tid & 31;

    sh[tid >> 5][tid & 31] = d_hbuf[(size_t)(m0 + (tid >> 5)) * HH + (tid & 31)];
    __syncthreads();

    const float db = dynb[j];
    float acc[DROWS];
#pragma unroll
    for (int i = 0; i < DROWS; ++i) acc[i] = 0.f;
#pragma unroll
    for (int kk = 0; kk < HH / 2; ++kk) {
        float2 w = d_dynWT2[kk * ZF + j];
#pragma unroll
        for (int i = 0; i < DROWS; ++i) {
            acc[i] = fmaf(w.x, sh[i][2 * kk], acc[i]);
            acc[i] = fmaf(w.y, sh[i][2 * kk + 1], acc[i]);
        }
    }
    const uint32_t k0 = d_keys[2 * TT], k1 = d_keys[2 * TT + 1];
#pragma unroll
    for (int i = 0; i < DROWS; ++i) {
        uint32_t e = (uint32_t)((m0 + i) * ZF + j);
        uint32_t b0, b1;
        tf2x32_full(k0, k1, 0u, e, b0, b1);
        float v = (acc[i] + db) + gumbel32(b0 ^ b1);
        int bi = warp_argmax_fast(v);
        zp[(size_t)(m0 + i) * ZF + j] = (lane == bi) ? 1.0f : 0.0f;
    }
}

/* -------- launch -------- */
extern "C" void kernel_launch(void *const *d_in, const int *in_sizes, int n_in,
                              void *d_out, int out_size) {
    const float *x    = (const float *)d_in[0];
    const float *a    = (const float *)d_in[1];
    const float *h0   = (const float *)d_in[2];
    const float *encW = (const float *)d_in[3];
    const float *encb = (const float *)d_in[4];
    const float *Wih  = (const float *)d_in[5];
    const float *Whh  = (const float *)d_in[6];
    const float *bih  = (const float *)d_in[7];
    const float *bhh  = (const float *)d_in[8];
    const float *decW = (const float *)d_in[9];
    const float *decb = (const float *)d_in[10];
    const float *dynW = (const float *)d_in[11];
    const float *dynb = (const float *)d_in[12];
    const float *rewW = (const float *)d_in[13];
    const float *conW = (const float *)d_in[14];
    const float *conb = (const float *)d_in[15];

    float *out      = (float *)d_out;
    float *x_logits = out;                 /* 64*1024*10   = 655360   */
    float *r_loc    = out + 655360;        /* 64*1024*1    = 65536    */
    float *c_logits = out + 720896;        /* 64*1024*1    = 65536    */
    float *z        = out + 786432;        /* 64*1024*1024 = 67108864 */
    float *zp       = out + 67895296;      /* 64*1024*1024 = 67108864 */

    prep_kernel<<<(PREP_TOTAL + 255) / 256, 256>>>(encW, dynW, Wih, Whh);
    gz_kernel<<<TT * 512, 256>>>();
    rssm_scan<<<SCAN_GRID, 1024>>>(x, a, h0, encb, bih, bhh, z);
    head_kernel<<<(TT * NROW + 127) / 128, 128>>>(decW, decb, rewW, conW, conb,
                                                  x_logits, r_loc, c_logits);
    dyn_kernel<<<(TT * NROW / DROWS) * 4, 256>>>(dynb, zp);
}